// round 3
// baseline (speedup 1.0000x reference)
#include <cuda_runtime.h>
#include <cstdint>

// Problem: states [B=64, L=4096, D=256] f32; w [256] f32; b scalar f32.
// out[b,l] = reverse_cumsum_l( dot(states[b,l,:], w) + b )
// Strategy: kernel1 writes values into d_out (one warp per row, coalesced
// float4 loads, warp reduce). kernel2 does an in-place reverse cumsum per
// batch row (block scan). No scratch memory needed.

static constexpr int B = 64;
static constexpr int L = 4096;
static constexpr int D = 256;          // 64 float4 per row
static constexpr int ROWS = B * L;     // 262144

__global__ void __launch_bounds__(256)
dot_kernel(const float4* __restrict__ states4,
           const float4* __restrict__ w4,
           const float*  __restrict__ bias,
           float* __restrict__ out)
{
    int gwarp = (blockIdx.x * blockDim.x + threadIdx.x) >> 5;
    int lane  = threadIdx.x & 31;
    if (gwarp >= ROWS) return;

    const float4* row = states4 + (size_t)gwarp * (D / 4);

    // 32 lanes x 2 float4 = 256 floats, fully coalesced
    float4 a0 = row[lane];
    float4 a1 = row[lane + 32];
    float4 w0 = w4[lane];
    float4 w1 = w4[lane + 32];

    float s = a0.x * w0.x + a0.y * w0.y + a0.z * w0.z + a0.w * w0.w
            + a1.x * w1.x + a1.y * w1.y + a1.z * w1.z + a1.w * w1.w;

    // warp reduce
    #pragma unroll
    for (int off = 16; off > 0; off >>= 1)
        s += __shfl_xor_sync(0xFFFFFFFFu, s, off);

    if (lane == 0)
        out[gwarp] = s + *bias;
}

// In-place reverse cumulative sum along L for each batch row.
// grid = B blocks, 128 threads, each thread owns 32 contiguous elements.
__global__ void __launch_bounds__(128)
rcumsum_kernel(float* __restrict__ data)
{
    constexpr int T   = 128;
    constexpr int PER = 32;            // L / T

    int b = blockIdx.x;
    int t = threadIdx.x;
    float* row = data + (size_t)b * L;

    // Thread t owns reverse-ranks [t*PER, (t+1)*PER): memory indices
    // [L - (t+1)*PER, L - t*PER), i.e. higher t = closer to the front.
    int base = L - (t + 1) * PER;

    float4 v4[PER / 4];
    #pragma unroll
    for (int i = 0; i < PER / 4; i++)
        v4[i] = reinterpret_cast<const float4*>(row + base)[i];
    float* v = reinterpret_cast<float*>(v4);

    float total = 0.f;
    #pragma unroll
    for (int k = 0; k < PER; k++) total += v[k];

    // Exclusive scan of thread totals in t-order (threads with smaller t
    // own elements NEARER the end, whose sums must be added to thread t's
    // chunk? No: reverse cumsum q[l] = sum_{j>=l} v[j]. Thread t's chunk
    // needs the sum of all reverse-ranks < t*PER, i.e. totals of threads
    // 0..t-1.)
    __shared__ float warp_sums[T / 32];
    int lane = t & 31;
    int wid  = t >> 5;

    // inclusive scan within warp
    float incl = total;
    #pragma unroll
    for (int off = 1; off < 32; off <<= 1) {
        float n = __shfl_up_sync(0xFFFFFFFFu, incl, off);
        if (lane >= off) incl += n;
    }
    if (lane == 31) warp_sums[wid] = incl;
    __syncthreads();

    float warp_off = 0.f;
    #pragma unroll
    for (int wpre = 0; wpre < T / 32; wpre++)
        if (wpre < wid) warp_off += warp_sums[wpre];

    float offset = warp_off + (incl - total);   // exclusive prefix for this thread

    // within-chunk reverse cumsum: iterate k from high index (low reverse
    // rank comes later... careful): element at memory index base+k has
    // reverse-rank t*PER + (PER-1-k). q[base+k] = offset + sum_{j>=k} v[j].
    float acc = offset;
    #pragma unroll
    for (int k = PER - 1; k >= 0; k--) {
        acc += v[k];
        v[k] = acc;
    }

    #pragma unroll
    for (int i = 0; i < PER / 4; i++)
        reinterpret_cast<float4*>(row + base)[i] = v4[i];
}

extern "C" void kernel_launch(void* const* d_in, const int* in_sizes, int n_in,
                              void* d_out, int out_size)
{
    const float4* states4 = (const float4*)d_in[0];
    const float4* w4      = (const float4*)d_in[1];
    const float*  bias    = (const float*)d_in[2];
    float* out = (float*)d_out;

    // kernel 1: 1 warp per (b,l) row; 8 warps/block of 256 threads
    int blocks = ROWS / 8;   // 32768
    dot_kernel<<<blocks, 256>>>(states4, w4, bias, out);

    // kernel 2: in-place reverse cumsum per batch row
    rcumsum_kernel<<<B, 128>>>(out);
}